// round 12
// baseline (speedup 1.0000x reference)
#include <cuda_runtime.h>
#include <cuda_fp16.h>
#include <cstdint>

// ---------------------------------------------------------------------------
// SphericalLinear on GB300 (PTX target sm_103 plain: no tcgen05 available).
// R12: SINGLE-term fp16 GEMM: out ~= fp16(A) * fp16(B). Error = A-rounding +
//      B-rounding ~ sqrt(2)*2.17e-4 ~ 3.1e-4 << 1e-3. HMMA count halves vs
//      R11 (2048/CTA). Structure = R10/R11: 3-stage cp.async ring, one
//      __syncthreads/chunk, 64B swizzled SMEM rows, 2 CTAs/SM.
// ---------------------------------------------------------------------------

#define NFILT   4
#define C_IN    256
#define C_OUT   512
#define TILE_M  128
#define TILE_N  128
#define KC      32
#define NCHUNKS (C_IN / KC)          // 8
#define NSTAGE  3
#define MAXP    65536
#define CAP     32768                 // fixed bucket capacity (rows)
#define CAPT    (CAP / TILE_M)        // 256 tiles per filter
#define PADROWS (NFILT * CAP)         // 131072
#define THREADS 256

// SMEM: fp16 rows of 32 elems = 64B, XOR chunk swizzle c^=((r>>1)&3)
#define MAT_SZ  (TILE_M * 64)         // 8192 B per matrix
#define OFF_AH  0
#define OFF_BH  (MAT_SZ)
#define STAGE_SZ (2 * MAT_SZ)         // 16384
#define SM_PERM  0
#define SM_TILE  1024
#define SMEM_TOTAL (SM_TILE + NSTAGE * STAGE_SZ)   // 50176 B (2/SM easily)

// ---- device scratch --------------------------------------------------------
__device__ int d_perm[PADROWS];
__device__ int d_fill[NFILT];
__device__ __half d_Ahi[(size_t)PADROWS * C_IN];
__device__ __half d_Whi[(size_t)NFILT * C_OUT * C_IN];

// ---- helpers ---------------------------------------------------------------
__device__ __forceinline__ uint32_t smem_u32(const void* p) {
    uint32_t a;
    asm("{ .reg .u64 t; cvta.to.shared.u64 t, %1; cvt.u32.u64 %0, t; }" : "=r"(a) : "l"(p));
    return a;
}
__device__ __forceinline__ void cp16(uint32_t dst, const void* src) {
    asm volatile("cp.async.cg.shared.global [%0], [%1], 16;" :: "r"(dst), "l"(src) : "memory");
}
#define CP_COMMIT() asm volatile("cp.async.commit_group;" ::: "memory")
#define CP_WAIT1()  asm volatile("cp.async.wait_group 1;" ::: "memory")

__device__ __forceinline__ void ldsm4(uint32_t* r, uint32_t addr) {
    asm volatile("ldmatrix.sync.aligned.m8n8.x4.shared.b16 {%0,%1,%2,%3}, [%4];"
                 : "=r"(r[0]), "=r"(r[1]), "=r"(r[2]), "=r"(r[3]) : "r"(addr));
}
__device__ __forceinline__ void mma_f16(float* c, const uint32_t* a,
                                        uint32_t b0, uint32_t b1) {
    asm volatile("mma.sync.aligned.m16n8k16.row.col.f32.f16.f16.f32 "
                 "{%0,%1,%2,%3}, {%4,%5,%6,%7}, {%8,%9}, {%0,%1,%2,%3};"
                 : "+f"(c[0]), "+f"(c[1]), "+f"(c[2]), "+f"(c[3])
                 : "r"(a[0]), "r"(a[1]), "r"(a[2]), "r"(a[3]), "r"(b0), "r"(b1));
}

// fp32x8 -> fp16x8 packed
__device__ __forceinline__ uint4 cvt8_h(float4 v0, float4 v1) {
    uint4 hi;
    __half2 h0 = __floats2half2_rn(v0.x, v0.y);
    __half2 h1 = __floats2half2_rn(v0.z, v0.w);
    __half2 h2 = __floats2half2_rn(v1.x, v1.y);
    __half2 h3 = __floats2half2_rn(v1.z, v1.w);
    hi.x = *reinterpret_cast<uint32_t*>(&h0);
    hi.y = *reinterpret_cast<uint32_t*>(&h1);
    hi.z = *reinterpret_cast<uint32_t*>(&h2);
    hi.w = *reinterpret_cast<uint32_t*>(&h3);
    return hi;
}

// ---- front-end kernels -----------------------------------------------------
__global__ void reset_kernel() {
    int t = threadIdx.x;
    if (t < NFILT) d_fill[t] = 0;
}

__global__ void classify_scatter_kernel(const float* __restrict__ xyz, int P) {
    __shared__ int sc[NFILT];
    __shared__ int sbase[NFILT];
    int tid = threadIdx.x;
    if (tid < NFILT) sc[tid] = 0;
    __syncthreads();
    int p = blockIdx.x * blockDim.x + tid;
    int f = 0, rank = 0;
    if (p < P) {
        float x = xyz[3 * p + 0], y = xyz[3 * p + 1], z = xyz[3 * p + 2];
        float r = sqrtf(x * x + y * y + z * z);
        if      (r < 1.0f)   f = 0;
        else if (r < 1.5f)   f = 1;
        else if (r < 2.0f)   f = 2;
        else if (r < 100.0f) f = 3;
        else                 f = 0;   // argmax of all-False -> 0 (matches jnp)
        rank = atomicAdd(&sc[f], 1);
    }
    __syncthreads();
    if (tid < NFILT) sbase[tid] = (sc[tid] != 0) ? atomicAdd(&d_fill[tid], sc[tid]) : 0;
    __syncthreads();
    if (p < P) d_perm[f * CAP + sbase[f] + rank] = p;
}

__global__ void pack_all_kernel(const float* __restrict__ feat,
                                const float* __restrict__ weight,
                                int featBlocks) {
    int tid = threadIdx.x;
    int col = (tid & 31) * 8;
    if ((int)blockIdx.x < featBlocks) {
        int q = blockIdx.x * 8 + (tid >> 5);       // padded global row
        int f = q >> 15;                           // q / CAP
        int local = q & (CAP - 1);
        int cnt = d_fill[f];
        int rcnt = (cnt + TILE_M - 1) & ~(TILE_M - 1);
        if (local >= rcnt) return;                 // beyond used+padded region
        uint4 hi = {0, 0, 0, 0};
        if (local < cnt) {
            int p = d_perm[q];
            const float4* src = (const float4*)(feat + (size_t)p * C_IN + col);
            hi = cvt8_h(src[0], src[1]);
        }
        *(uint4*)(d_Ahi + (size_t)q * C_IN + col) = hi;
    } else {
        int q = (blockIdx.x - featBlocks) * 8 + (tid >> 5);   // weight row
        if (q >= NFILT * C_OUT) return;
        const float4* src = (const float4*)(weight + (size_t)q * C_IN + col);
        *(uint4*)(d_Whi + (size_t)q * C_IN + col) = cvt8_h(src[0], src[1]);
    }
}

// ---- GEMM ------------------------------------------------------------------
__global__ void __launch_bounds__(THREADS, 2)
gemm_mma_kernel(const float* __restrict__ bias, float* __restrict__ out) {
    extern __shared__ char smem[];
    const int tid = threadIdx.x;
    const int lane = tid & 31;
    const int wid = tid >> 5;
    const int wm = wid >> 2;          // 0..1
    const int wn = wid & 3;           // 0..3
    const int by = blockIdx.y;

    const int f = blockIdx.x >> 8;                 // blockIdx.x / CAPT
    const int rowbase = blockIdx.x * TILE_M;       // padded global row base
    int nval = d_fill[f] - (int)((blockIdx.x & (CAPT - 1)) * TILE_M);
    if (nval <= 0) return;
    if (nval > TILE_M) nval = TILE_M;

    int* sPerm = (int*)(smem + SM_PERM);
    if (tid < TILE_M) {
        sPerm[tid] = (tid < nval) ? d_perm[rowbase + tid] : d_perm[rowbase];
    }

    const uint32_t sb = smem_u32(smem) + SM_TILE;

    const char* srcA_h = (const char*)(d_Ahi + (size_t)rowbase * C_IN);
    const size_t wrow = ((size_t)f * C_OUT + (size_t)by * TILE_N) * C_IN;
    const char* srcB_h = (const char*)(d_Whi + wrow);

    // stage loader: 2 matrices x 128 rows x 4 swizzled 16B chunks
    auto load_stage = [&](int c, int s) {
        const int ktB = c * KC * 2;                 // byte offset into 512B rows
        const uint32_t base = sb + s * STAGE_SZ;
        #pragma unroll
        for (int it = 0; it < 2; it++) {
            int idx = it * THREADS + tid;           // 0..511
            int r = idx >> 2;
            int cc = idx & 3;
            int sw = (cc ^ ((r >> 1) & 3)) * 16;
            uint32_t d0 = base + r * 64 + sw;
            size_t   so = (size_t)r * 512 + ktB + cc * 16;
            cp16(d0 + OFF_AH, srcA_h + so);
            cp16(d0 + OFF_BH, srcB_h + so);
        }
        CP_COMMIT();
    };

    load_stage(0, 0);
    load_stage(1, 1);

    // ldmatrix lane address components: swizzle selector per-lane constant;
    // chunk offsets precomputed for both k16 phases.
    const int rA = ((lane >> 3) & 1) * 8 + (lane & 7);
    const int kA = (lane >> 4);
    const int rB = (lane >> 4) * 8 + (lane & 7);
    const int kB = ((lane >> 3) & 1);
    const int rowA0 = wm * 64 + rA;
    const int rowB0 = wn * 32 + rB;
    const uint32_t adA0 = (uint32_t)(rowA0 * 64 + ((kA ^ ((rowA0 >> 1) & 3)) * 16));
    const uint32_t adA1 = (uint32_t)(rowA0 * 64 + (((2 + kA) ^ ((rowA0 >> 1) & 3)) * 16));
    const uint32_t adB0 = (uint32_t)(rowB0 * 64 + ((kB ^ ((rowB0 >> 1) & 3)) * 16));
    const uint32_t adB1 = (uint32_t)(rowB0 * 64 + (((2 + kB) ^ ((rowB0 >> 1) & 3)) * 16));

    float acc[4][4][4];
    #pragma unroll
    for (int i = 0; i < 4; i++)
        #pragma unroll
        for (int j = 0; j < 4; j++)
            #pragma unroll
            for (int e = 0; e < 4; e++) acc[i][j][e] = 0.0f;

    #pragma unroll
    for (int c = 0; c < NCHUNKS; c++) {
        const int s = c % NSTAGE;                  // static after full unroll
        const uint32_t base = sb + s * STAGE_SZ;
        CP_WAIT1();
        __syncthreads();                           // single barrier per chunk
        if (c + 2 < NCHUNKS) load_stage(c + 2, (c + 2) % NSTAGE);

        #pragma unroll
        for (int k16 = 0; k16 < 2; k16++) {
            const uint32_t aoff = base + (k16 ? adA1 : adA0);
            const uint32_t boff = base + (k16 ? adB1 : adB0);
            uint32_t ah[4][4];
            uint32_t bh[2][4];
            #pragma unroll
            for (int mi = 0; mi < 4; mi++) {
                ldsm4(ah[mi], aoff + mi * (16 * 64) + OFF_AH);
            }
            #pragma unroll
            for (int nj = 0; nj < 2; nj++) {
                ldsm4(bh[nj], boff + nj * (16 * 64) + OFF_BH);
            }
            #pragma unroll
            for (int mi = 0; mi < 4; mi++) {
                #pragma unroll
                for (int n8 = 0; n8 < 4; n8++) {
                    const int nj = n8 >> 1, h = (n8 & 1) * 2;
                    mma_f16(acc[mi][n8], ah[mi], bh[nj][h], bh[nj][h + 1]);
                }
            }
        }
    }

    // ---- epilogue: bias + scattered stores ----
    const int g = lane >> 2;
    const int a2 = (lane & 3) * 2;
    float2 bv[4];
    #pragma unroll
    for (int ni = 0; ni < 4; ni++)
        bv[ni] = *(const float2*)(bias + (size_t)f * C_OUT + by * TILE_N + wn * 32 + ni * 8 + a2);

    #pragma unroll
    for (int mi = 0; mi < 4; mi++) {
        #pragma unroll
        for (int half = 0; half < 2; half++) {
            int ml = wm * 64 + mi * 16 + g + half * 8;
            if (ml < nval) {
                float* orow = out + (size_t)sPerm[ml] * C_OUT + by * TILE_N + wn * 32;
                #pragma unroll
                for (int ni = 0; ni < 4; ni++) {
                    float2 v;
                    v.x = acc[mi][ni][half * 2 + 0] + bv[ni].x;
                    v.y = acc[mi][ni][half * 2 + 1] + bv[ni].y;
                    *(float2*)(orow + ni * 8 + a2) = v;
                }
            }
        }
    }
}

// ---------------------------------------------------------------------------
extern "C" void kernel_launch(void* const* d_in, const int* in_sizes, int n_in,
                              void* d_out, int out_size) {
    const float* feat   = (const float*)d_in[0];
    const float* xyz    = (const float*)d_in[1];
    const float* weight = (const float*)d_in[2];
    const float* bias   = (const float*)d_in[3];
    float* out = (float*)d_out;

    const int P = in_sizes[0] / C_IN;

    cudaFuncSetAttribute(gemm_mma_kernel,
                         cudaFuncAttributeMaxDynamicSharedMemorySize, SMEM_TOTAL);

    reset_kernel<<<1, 32>>>();
    classify_scatter_kernel<<<(P + 255) / 256, 256>>>(xyz, P);

    const int featBlocks = PADROWS / 8;
    const int wBlocks = (NFILT * C_OUT) / 8;
    pack_all_kernel<<<featBlocks + wBlocks, 256>>>(feat, weight, featBlocks);

    dim3 grid(NFILT * CAPT, C_OUT / TILE_N);
    gemm_mma_kernel<<<grid, THREADS, SMEM_TOTAL>>>(bias, out);
}

// round 14
// speedup vs baseline: 1.4724x; 1.4724x over previous
#include <cuda_runtime.h>
#include <cuda_fp16.h>
#include <cstdint>

// ---------------------------------------------------------------------------
// SphericalLinear on GB300 (PTX target sm_103 plain: no tcgen05 available).
// R14: R13 (single-term fp16, KC=64, 4 chunks, 3-stage ring, 2 CTAs/SM) with
//      the cp.async wait FIXED: the last chunk must use wait_group 0 (its own
//      load is the only pending group; wait_group 1 skips it -> data race that
//      R13 exposed and R10-R12 carried latently).
// ---------------------------------------------------------------------------

#define NFILT   4
#define C_IN    256
#define C_OUT   512
#define TILE_M  128
#define TILE_N  128
#define KC      64
#define NCHUNKS (C_IN / KC)          // 4
#define NSTAGE  3
#define MAXP    65536
#define CAP     32768                 // fixed bucket capacity (rows)
#define CAPT    (CAP / TILE_M)        // 256 tiles per filter
#define PADROWS (NFILT * CAP)         // 131072
#define THREADS 256

// SMEM: fp16 rows of 64 elems = 128B = 8 chunks of 16B, swizzle c^=(r&7)
#define MAT_SZ  (TILE_M * 128)        // 16384 B per matrix
#define OFF_AH  0
#define OFF_BH  (MAT_SZ)
#define STAGE_SZ (2 * MAT_SZ)         // 32768
#define SM_PERM  0
#define SM_TILE  1024
#define SMEM_TOTAL (SM_TILE + NSTAGE * STAGE_SZ)   // 99328 B (2/SM fits)

// ---- device scratch --------------------------------------------------------
__device__ int d_perm[PADROWS];
__device__ int d_fill[NFILT];
__device__ __half d_Ahi[(size_t)PADROWS * C_IN];
__device__ __half d_Whi[(size_t)NFILT * C_OUT * C_IN];

// ---- helpers ---------------------------------------------------------------
__device__ __forceinline__ uint32_t smem_u32(const void* p) {
    uint32_t a;
    asm("{ .reg .u64 t; cvta.to.shared.u64 t, %1; cvt.u32.u64 %0, t; }" : "=r"(a) : "l"(p));
    return a;
}
__device__ __forceinline__ void cp16(uint32_t dst, const void* src) {
    asm volatile("cp.async.cg.shared.global [%0], [%1], 16;" :: "r"(dst), "l"(src) : "memory");
}
#define CP_COMMIT() asm volatile("cp.async.commit_group;" ::: "memory")
#define CP_WAIT1()  asm volatile("cp.async.wait_group 1;" ::: "memory")
#define CP_WAIT0()  asm volatile("cp.async.wait_group 0;" ::: "memory")

__device__ __forceinline__ void ldsm4(uint32_t* r, uint32_t addr) {
    asm volatile("ldmatrix.sync.aligned.m8n8.x4.shared.b16 {%0,%1,%2,%3}, [%4];"
                 : "=r"(r[0]), "=r"(r[1]), "=r"(r[2]), "=r"(r[3]) : "r"(addr));
}
__device__ __forceinline__ void mma_f16(float* c, const uint32_t* a,
                                        uint32_t b0, uint32_t b1) {
    asm volatile("mma.sync.aligned.m16n8k16.row.col.f32.f16.f16.f32 "
                 "{%0,%1,%2,%3}, {%4,%5,%6,%7}, {%8,%9}, {%0,%1,%2,%3};"
                 : "+f"(c[0]), "+f"(c[1]), "+f"(c[2]), "+f"(c[3])
                 : "r"(a[0]), "r"(a[1]), "r"(a[2]), "r"(a[3]), "r"(b0), "r"(b1));
}

// fp32x8 -> fp16x8 packed
__device__ __forceinline__ uint4 cvt8_h(float4 v0, float4 v1) {
    uint4 hi;
    __half2 h0 = __floats2half2_rn(v0.x, v0.y);
    __half2 h1 = __floats2half2_rn(v0.z, v0.w);
    __half2 h2 = __floats2half2_rn(v1.x, v1.y);
    __half2 h3 = __floats2half2_rn(v1.z, v1.w);
    hi.x = *reinterpret_cast<uint32_t*>(&h0);
    hi.y = *reinterpret_cast<uint32_t*>(&h1);
    hi.z = *reinterpret_cast<uint32_t*>(&h2);
    hi.w = *reinterpret_cast<uint32_t*>(&h3);
    return hi;
}

// ---- front-end kernels -----------------------------------------------------
__global__ void reset_kernel() {
    int t = threadIdx.x;
    if (t < NFILT) d_fill[t] = 0;
}

__global__ void classify_scatter_kernel(const float* __restrict__ xyz, int P) {
    __shared__ int sc[NFILT];
    __shared__ int sbase[NFILT];
    int tid = threadIdx.x;
    if (tid < NFILT) sc[tid] = 0;
    __syncthreads();
    int p = blockIdx.x * blockDim.x + tid;
    int f = 0, rank = 0;
    if (p < P) {
        float x = xyz[3 * p + 0], y = xyz[3 * p + 1], z = xyz[3 * p + 2];
        float r = sqrtf(x * x + y * y + z * z);
        if      (r < 1.0f)   f = 0;
        else if (r < 1.5f)   f = 1;
        else if (r < 2.0f)   f = 2;
        else if (r < 100.0f) f = 3;
        else                 f = 0;   // argmax of all-False -> 0 (matches jnp)
        rank = atomicAdd(&sc[f], 1);
    }
    __syncthreads();
    if (tid < NFILT) sbase[tid] = (sc[tid] != 0) ? atomicAdd(&d_fill[tid], sc[tid]) : 0;
    __syncthreads();
    if (p < P) d_perm[f * CAP + sbase[f] + rank] = p;
}

__global__ void pack_all_kernel(const float* __restrict__ feat,
                                const float* __restrict__ weight,
                                int featBlocks) {
    int tid = threadIdx.x;
    int col = (tid & 31) * 8;
    if ((int)blockIdx.x < featBlocks) {
        int q = blockIdx.x * 8 + (tid >> 5);       // padded global row
        int f = q >> 15;                           // q / CAP
        int local = q & (CAP - 1);
        int cnt = d_fill[f];
        int rcnt = (cnt + TILE_M - 1) & ~(TILE_M - 1);
        if (local >= rcnt) return;                 // beyond used+padded region
        uint4 hi = {0, 0, 0, 0};
        if (local < cnt) {
            int p = d_perm[q];
            const float4* src = (const float4*)(feat + (size_t)p * C_IN + col);
            hi = cvt8_h(src[0], src[1]);
        }
        *(uint4*)(d_Ahi + (size_t)q * C_IN + col) = hi;
    } else {
        int q = (blockIdx.x - featBlocks) * 8 + (tid >> 5);   // weight row
        if (q >= NFILT * C_OUT) return;
        const float4* src = (const float4*)(weight + (size_t)q * C_IN + col);
        *(uint4*)(d_Whi + (size_t)q * C_IN + col) = cvt8_h(src[0], src[1]);
    }
}

// ---- GEMM ------------------------------------------------------------------
__global__ void __launch_bounds__(THREADS, 2)
gemm_mma_kernel(const float* __restrict__ bias, float* __restrict__ out) {
    extern __shared__ char smem[];
    const int tid = threadIdx.x;
    const int lane = tid & 31;
    const int wid = tid >> 5;
    const int wm = wid >> 2;          // 0..1
    const int wn = wid & 3;           // 0..3
    const int by = blockIdx.y;

    const int f = blockIdx.x >> 8;                 // blockIdx.x / CAPT
    const int rowbase = blockIdx.x * TILE_M;       // padded global row base
    int nval = d_fill[f] - (int)((blockIdx.x & (CAPT - 1)) * TILE_M);
    if (nval <= 0) return;
    if (nval > TILE_M) nval = TILE_M;

    int* sPerm = (int*)(smem + SM_PERM);
    if (tid < TILE_M) {
        sPerm[tid] = (tid < nval) ? d_perm[rowbase + tid] : d_perm[rowbase];
    }

    const uint32_t sb = smem_u32(smem) + SM_TILE;

    const char* srcA_h = (const char*)(d_Ahi + (size_t)rowbase * C_IN);
    const size_t wrow = ((size_t)f * C_OUT + (size_t)by * TILE_N) * C_IN;
    const char* srcB_h = (const char*)(d_Whi + wrow);

    // stage loader: 2 matrices x 128 rows x 8 swizzled 16B chunks
    auto load_stage = [&](int c, int s) {
        const int ktB = c * KC * 2;                 // byte offset into 512B rows
        const uint32_t base = sb + s * STAGE_SZ;
        #pragma unroll
        for (int it = 0; it < 4; it++) {
            int idx = it * THREADS + tid;           // 0..1023
            int r = idx >> 3;
            int cc = idx & 7;
            int sw = (cc ^ (r & 7)) * 16;
            uint32_t d0 = base + r * 128 + sw;
            size_t   so = (size_t)r * 512 + ktB + cc * 16;
            cp16(d0 + OFF_AH, srcA_h + so);
            cp16(d0 + OFF_BH, srcB_h + so);
        }
        CP_COMMIT();
    };

    load_stage(0, 0);
    load_stage(1, 1);

    // ldmatrix lane address components: swizzle selector (row&7) is per-lane
    // constant (16-row steps preserve it). Chunk index per k16 = k16*2 + kA.
    const int rA = ((lane >> 3) & 1) * 8 + (lane & 7);
    const int kA = (lane >> 4);
    const int rB = (lane >> 4) * 8 + (lane & 7);
    const int kB = ((lane >> 3) & 1);
    const int rowA0 = wm * 64 + rA;
    const int rowB0 = wn * 32 + rB;
    const int swzA = rowA0 & 7;
    const int swzB = rowB0 & 7;
    uint32_t adA[4], adB[4];
    #pragma unroll
    for (int k16 = 0; k16 < 4; k16++) {
        adA[k16] = (uint32_t)(rowA0 * 128 + (((k16 * 2 + kA) ^ swzA) * 16));
        adB[k16] = (uint32_t)(rowB0 * 128 + (((k16 * 2 + kB) ^ swzB) * 16));
    }

    float acc[4][4][4];
    #pragma unroll
    for (int i = 0; i < 4; i++)
        #pragma unroll
        for (int j = 0; j < 4; j++)
            #pragma unroll
            for (int e = 0; e < 4; e++) acc[i][j][e] = 0.0f;

    #pragma unroll
    for (int c = 0; c < NCHUNKS; c++) {
        const int s = c % NSTAGE;                  // static after full unroll
        const uint32_t base = sb + s * STAGE_SZ;
        // Wait accounting: at chunk c, loads issued = min(c+2, NCHUNKS);
        // group c must be complete -> allowed pending = issued-(c+1):
        // 1 for all chunks except the LAST, which must wait for everything.
        if (c == NCHUNKS - 1) { CP_WAIT0(); } else { CP_WAIT1(); }
        __syncthreads();                           // single barrier per chunk
        if (c + 2 < NCHUNKS) load_stage(c + 2, (c + 2) % NSTAGE);

        #pragma unroll
        for (int k16 = 0; k16 < 4; k16++) {
            const uint32_t aoff = base + adA[k16];
            const uint32_t boff = base + adB[k16];
            uint32_t ah[4][4];
            uint32_t bh[2][4];
            #pragma unroll
            for (int mi = 0; mi < 4; mi++) {
                ldsm4(ah[mi], aoff + mi * (16 * 128) + OFF_AH);
            }
            #pragma unroll
            for (int nj = 0; nj < 2; nj++) {
                ldsm4(bh[nj], boff + nj * (16 * 128) + OFF_BH);
            }
            #pragma unroll
            for (int mi = 0; mi < 4; mi++) {
                #pragma unroll
                for (int n8 = 0; n8 < 4; n8++) {
                    const int nj = n8 >> 1, h = (n8 & 1) * 2;
                    mma_f16(acc[mi][n8], ah[mi], bh[nj][h], bh[nj][h + 1]);
                }
            }
        }
    }

    // ---- epilogue: bias + scattered stores ----
    const int g = lane >> 2;
    const int a2 = (lane & 3) * 2;
    float2 bv[4];
    #pragma unroll
    for (int ni = 0; ni < 4; ni++)
        bv[ni] = *(const float2*)(bias + (size_t)f * C_OUT + by * TILE_N + wn * 32 + ni * 8 + a2);

    #pragma unroll
    for (int mi = 0; mi < 4; mi++) {
        #pragma unroll
        for (int half = 0; half < 2; half++) {
            int ml = wm * 64 + mi * 16 + g + half * 8;
            if (ml < nval) {
                float* orow = out + (size_t)sPerm[ml] * C_OUT + by * TILE_N + wn * 32;
                #pragma unroll
                for (int ni = 0; ni < 4; ni++) {
                    float2 v;
                    v.x = acc[mi][ni][half * 2 + 0] + bv[ni].x;
                    v.y = acc[mi][ni][half * 2 + 1] + bv[ni].y;
                    *(float2*)(orow + ni * 8 + a2) = v;
                }
            }
        }
    }
}

// ---------------------------------------------------------------------------
extern "C" void kernel_launch(void* const* d_in, const int* in_sizes, int n_in,
                              void* d_out, int out_size) {
    const float* feat   = (const float*)d_in[0];
    const float* xyz    = (const float*)d_in[1];
    const float* weight = (const float*)d_in[2];
    const float* bias   = (const float*)d_in[3];
    float* out = (float*)d_out;

    const int P = in_sizes[0] / C_IN;

    cudaFuncSetAttribute(gemm_mma_kernel,
                         cudaFuncAttributeMaxDynamicSharedMemorySize, SMEM_TOTAL);

    reset_kernel<<<1, 32>>>();
    classify_scatter_kernel<<<(P + 255) / 256, 256>>>(xyz, P);

    const int featBlocks = PADROWS / 8;
    const int wBlocks = (NFILT * C_OUT) / 8;
    pack_all_kernel<<<featBlocks + wBlocks, 256>>>(feat, weight, featBlocks);

    dim3 grid(NFILT * CAPT, C_OUT / TILE_N);
    gemm_mma_kernel<<<grid, THREADS, SMEM_TOTAL>>>(bias, out);
}

// round 15
// speedup vs baseline: 1.4747x; 1.0016x over previous
#include <cuda_runtime.h>
#include <cuda_fp16.h>
#include <cstdint>

// ---------------------------------------------------------------------------
// SphericalLinear on GB300 (PTX target sm_103 plain: no tcgen05 available).
// R15: GEMM frozen at R14 (single-term fp16, KC=64, 3-stage cp.async ring,
//      one barrier/chunk, wait_group fix, 2 CTAs/SM — measured ~96% of the
//      fp32-acc HMMA pipe floor). Front-end trimmed: 512-thread classify &
//      pack blocks, padding zero-fill skipped, GEMM grid compacted to the
//      exact tile count (516) with runtime tile->filter decode.
// ---------------------------------------------------------------------------

#define NFILT   4
#define C_IN    256
#define C_OUT   512
#define TILE_M  128
#define TILE_N  128
#define KC      64
#define NCHUNKS (C_IN / KC)          // 4
#define NSTAGE  3
#define MAXP    65536
#define CAP     32768                 // fixed bucket capacity (rows)
#define PADROWS (NFILT * CAP)         // 131072
#define THREADS 256
#define XTILES  (MAXP / TILE_M + NFILT)   // 516: max total padded tiles

// SMEM: fp16 rows of 64 elems = 128B = 8 chunks of 16B, swizzle c^=(r&7)
#define MAT_SZ  (TILE_M * 128)        // 16384 B per matrix
#define OFF_AH  0
#define OFF_BH  (MAT_SZ)
#define STAGE_SZ (2 * MAT_SZ)         // 32768
#define SM_PERM  0
#define SM_TILE  1024
#define SMEM_TOTAL (SM_TILE + NSTAGE * STAGE_SZ)   // 99328 B (2/SM fits)

// ---- device scratch --------------------------------------------------------
__device__ int d_perm[PADROWS];
__device__ int d_fill[NFILT];
__device__ __half d_Ahi[(size_t)PADROWS * C_IN];
__device__ __half d_Whi[(size_t)NFILT * C_OUT * C_IN];

// ---- helpers ---------------------------------------------------------------
__device__ __forceinline__ uint32_t smem_u32(const void* p) {
    uint32_t a;
    asm("{ .reg .u64 t; cvta.to.shared.u64 t, %1; cvt.u32.u64 %0, t; }" : "=r"(a) : "l"(p));
    return a;
}
__device__ __forceinline__ void cp16(uint32_t dst, const void* src) {
    asm volatile("cp.async.cg.shared.global [%0], [%1], 16;" :: "r"(dst), "l"(src) : "memory");
}
#define CP_COMMIT() asm volatile("cp.async.commit_group;" ::: "memory")
#define CP_WAIT1()  asm volatile("cp.async.wait_group 1;" ::: "memory")
#define CP_WAIT0()  asm volatile("cp.async.wait_group 0;" ::: "memory")

__device__ __forceinline__ void ldsm4(uint32_t* r, uint32_t addr) {
    asm volatile("ldmatrix.sync.aligned.m8n8.x4.shared.b16 {%0,%1,%2,%3}, [%4];"
                 : "=r"(r[0]), "=r"(r[1]), "=r"(r[2]), "=r"(r[3]) : "r"(addr));
}
__device__ __forceinline__ void mma_f16(float* c, const uint32_t* a,
                                        uint32_t b0, uint32_t b1) {
    asm volatile("mma.sync.aligned.m16n8k16.row.col.f32.f16.f16.f32 "
                 "{%0,%1,%2,%3}, {%4,%5,%6,%7}, {%8,%9}, {%0,%1,%2,%3};"
                 : "+f"(c[0]), "+f"(c[1]), "+f"(c[2]), "+f"(c[3])
                 : "r"(a[0]), "r"(a[1]), "r"(a[2]), "r"(a[3]), "r"(b0), "r"(b1));
}

// fp32x8 -> fp16x8 packed
__device__ __forceinline__ uint4 cvt8_h(float4 v0, float4 v1) {
    uint4 hi;
    __half2 h0 = __floats2half2_rn(v0.x, v0.y);
    __half2 h1 = __floats2half2_rn(v0.z, v0.w);
    __half2 h2 = __floats2half2_rn(v1.x, v1.y);
    __half2 h3 = __floats2half2_rn(v1.z, v1.w);
    hi.x = *reinterpret_cast<uint32_t*>(&h0);
    hi.y = *reinterpret_cast<uint32_t*>(&h1);
    hi.z = *reinterpret_cast<uint32_t*>(&h2);
    hi.w = *reinterpret_cast<uint32_t*>(&h3);
    return hi;
}

// ---- front-end kernels -----------------------------------------------------
__global__ void reset_kernel() {
    int t = threadIdx.x;
    if (t < NFILT) d_fill[t] = 0;
}

__global__ void classify_scatter_kernel(const float* __restrict__ xyz, int P) {
    __shared__ int sc[NFILT];
    __shared__ int sbase[NFILT];
    int tid = threadIdx.x;
    if (tid < NFILT) sc[tid] = 0;
    __syncthreads();
    int p = blockIdx.x * blockDim.x + tid;
    int f = 0, rank = 0;
    if (p < P) {
        float x = xyz[3 * p + 0], y = xyz[3 * p + 1], z = xyz[3 * p + 2];
        float r = sqrtf(x * x + y * y + z * z);
        if      (r < 1.0f)   f = 0;
        else if (r < 1.5f)   f = 1;
        else if (r < 2.0f)   f = 2;
        else if (r < 100.0f) f = 3;
        else                 f = 0;   // argmax of all-False -> 0 (matches jnp)
        rank = atomicAdd(&sc[f], 1);
    }
    __syncthreads();
    if (tid < NFILT) sbase[tid] = (sc[tid] != 0) ? atomicAdd(&d_fill[tid], sc[tid]) : 0;
    __syncthreads();
    if (p < P) d_perm[f * CAP + sbase[f] + rank] = p;
}

// 512-thread blocks, one warp per row (16 rows/block). Padding rows are NOT
// written: they are only ever consumed masked by the GEMM epilogue and stay 0
// from device zero-init (deterministic across graph replays).
__global__ void pack_all_kernel(const float* __restrict__ feat,
                                const float* __restrict__ weight,
                                int featBlocks) {
    int tid = threadIdx.x;
    int col = (tid & 31) * 8;
    if ((int)blockIdx.x < featBlocks) {
        int q = blockIdx.x * 16 + (tid >> 5);      // padded global row
        int f = q >> 15;                           // q / CAP
        int local = q & (CAP - 1);
        if (local >= d_fill[f]) return;            // beyond used region
        int p = d_perm[q];
        const float4* src = (const float4*)(feat + (size_t)p * C_IN + col);
        *(uint4*)(d_Ahi + (size_t)q * C_IN + col) = cvt8_h(src[0], src[1]);
    } else {
        int q = (blockIdx.x - featBlocks) * 16 + (tid >> 5);   // weight row
        if (q >= NFILT * C_OUT) return;
        const float4* src = (const float4*)(weight + (size_t)q * C_IN + col);
        *(uint4*)(d_Whi + (size_t)q * C_IN + col) = cvt8_h(src[0], src[1]);
    }
}

// ---- GEMM ------------------------------------------------------------------
__global__ void __launch_bounds__(THREADS, 2)
gemm_mma_kernel(const float* __restrict__ bias, float* __restrict__ out) {
    extern __shared__ char smem[];
    const int tid = threadIdx.x;
    const int lane = tid & 31;
    const int wid = tid >> 5;
    const int wm = wid >> 2;          // 0..1
    const int wn = wid & 3;           // 0..3
    const int by = blockIdx.y;

    // compact tile -> (filter, local tile) decode from bucket fills
    const int c0 = (d_fill[0] + TILE_M - 1) >> 7;
    const int c1 = (d_fill[1] + TILE_M - 1) >> 7;
    const int c2 = (d_fill[2] + TILE_M - 1) >> 7;
    const int c3 = (d_fill[3] + TILE_M - 1) >> 7;
    const int t = blockIdx.x;
    int f, lt;
    if      (t < c0)                { f = 0; lt = t; }
    else if (t < c0 + c1)           { f = 1; lt = t - c0; }
    else if (t < c0 + c1 + c2)      { f = 2; lt = t - c0 - c1; }
    else if (t < c0 + c1 + c2 + c3) { f = 3; lt = t - c0 - c1 - c2; }
    else return;

    const int rowbase = f * CAP + lt * TILE_M;     // padded global row base
    int nval = d_fill[f] - lt * TILE_M;
    if (nval > TILE_M) nval = TILE_M;

    int* sPerm = (int*)(smem + SM_PERM);
    if (tid < TILE_M) {
        sPerm[tid] = (tid < nval) ? d_perm[rowbase + tid] : d_perm[rowbase];
    }

    const uint32_t sb = smem_u32(smem) + SM_TILE;

    const char* srcA_h = (const char*)(d_Ahi + (size_t)rowbase * C_IN);
    const size_t wrow = ((size_t)f * C_OUT + (size_t)by * TILE_N) * C_IN;
    const char* srcB_h = (const char*)(d_Whi + wrow);

    // stage loader: 2 matrices x 128 rows x 8 swizzled 16B chunks
    auto load_stage = [&](int c, int s) {
        const int ktB = c * KC * 2;                 // byte offset into 512B rows
        const uint32_t base = sb + s * STAGE_SZ;
        #pragma unroll
        for (int it = 0; it < 4; it++) {
            int idx = it * THREADS + tid;           // 0..1023
            int r = idx >> 3;
            int cc = idx & 7;
            int sw = (cc ^ (r & 7)) * 16;
            uint32_t d0 = base + r * 128 + sw;
            size_t   so = (size_t)r * 512 + ktB + cc * 16;
            cp16(d0 + OFF_AH, srcA_h + so);
            cp16(d0 + OFF_BH, srcB_h + so);
        }
        CP_COMMIT();
    };

    load_stage(0, 0);
    load_stage(1, 1);

    // ldmatrix lane address components: swizzle selector (row&7) is per-lane
    // constant (16-row steps preserve it). Chunk index per k16 = k16*2 + kA.
    const int rA = ((lane >> 3) & 1) * 8 + (lane & 7);
    const int kA = (lane >> 4);
    const int rB = (lane >> 4) * 8 + (lane & 7);
    const int kB = ((lane >> 3) & 1);
    const int rowA0 = wm * 64 + rA;
    const int rowB0 = wn * 32 + rB;
    const int swzA = rowA0 & 7;
    const int swzB = rowB0 & 7;
    uint32_t adA[4], adB[4];
    #pragma unroll
    for (int k16 = 0; k16 < 4; k16++) {
        adA[k16] = (uint32_t)(rowA0 * 128 + (((k16 * 2 + kA) ^ swzA) * 16));
        adB[k16] = (uint32_t)(rowB0 * 128 + (((k16 * 2 + kB) ^ swzB) * 16));
    }

    float acc[4][4][4];
    #pragma unroll
    for (int i = 0; i < 4; i++)
        #pragma unroll
        for (int j = 0; j < 4; j++)
            #pragma unroll
            for (int e = 0; e < 4; e++) acc[i][j][e] = 0.0f;

    #pragma unroll
    for (int c = 0; c < NCHUNKS; c++) {
        const int s = c % NSTAGE;                  // static after full unroll
        const uint32_t base = sb + s * STAGE_SZ;
        // Wait accounting: at chunk c, loads issued = min(c+2, NCHUNKS);
        // group c must be complete -> allowed pending = issued-(c+1):
        // 1 for all chunks except the LAST, which must wait for everything.
        if (c == NCHUNKS - 1) { CP_WAIT0(); } else { CP_WAIT1(); }
        __syncthreads();                           // single barrier per chunk
        if (c + 2 < NCHUNKS) load_stage(c + 2, (c + 2) % NSTAGE);

        #pragma unroll
        for (int k16 = 0; k16 < 4; k16++) {
            const uint32_t aoff = base + adA[k16];
            const uint32_t boff = base + adB[k16];
            uint32_t ah[4][4];
            uint32_t bh[2][4];
            #pragma unroll
            for (int mi = 0; mi < 4; mi++) {
                ldsm4(ah[mi], aoff + mi * (16 * 128) + OFF_AH);
            }
            #pragma unroll
            for (int nj = 0; nj < 2; nj++) {
                ldsm4(bh[nj], boff + nj * (16 * 128) + OFF_BH);
            }
            #pragma unroll
            for (int mi = 0; mi < 4; mi++) {
                #pragma unroll
                for (int n8 = 0; n8 < 4; n8++) {
                    const int nj = n8 >> 1, h = (n8 & 1) * 2;
                    mma_f16(acc[mi][n8], ah[mi], bh[nj][h], bh[nj][h + 1]);
                }
            }
        }
    }

    // ---- epilogue: bias + scattered stores ----
    const int g = lane >> 2;
    const int a2 = (lane & 3) * 2;
    float2 bv[4];
    #pragma unroll
    for (int ni = 0; ni < 4; ni++)
        bv[ni] = *(const float2*)(bias + (size_t)f * C_OUT + by * TILE_N + wn * 32 + ni * 8 + a2);

    #pragma unroll
    for (int mi = 0; mi < 4; mi++) {
        #pragma unroll
        for (int half = 0; half < 2; half++) {
            int ml = wm * 64 + mi * 16 + g + half * 8;
            if (ml < nval) {
                float* orow = out + (size_t)sPerm[ml] * C_OUT + by * TILE_N + wn * 32;
                #pragma unroll
                for (int ni = 0; ni < 4; ni++) {
                    float2 v;
                    v.x = acc[mi][ni][half * 2 + 0] + bv[ni].x;
                    v.y = acc[mi][ni][half * 2 + 1] + bv[ni].y;
                    *(float2*)(orow + ni * 8 + a2) = v;
                }
            }
        }
    }
}

// ---------------------------------------------------------------------------
extern "C" void kernel_launch(void* const* d_in, const int* in_sizes, int n_in,
                              void* d_out, int out_size) {
    const float* feat   = (const float*)d_in[0];
    const float* xyz    = (const float*)d_in[1];
    const float* weight = (const float*)d_in[2];
    const float* bias   = (const float*)d_in[3];
    float* out = (float*)d_out;

    const int P = in_sizes[0] / C_IN;

    cudaFuncSetAttribute(gemm_mma_kernel,
                         cudaFuncAttributeMaxDynamicSharedMemorySize, SMEM_TOTAL);

    reset_kernel<<<1, 32>>>();
    classify_scatter_kernel<<<(P + 511) / 512, 512>>>(xyz, P);

    const int featBlocks = PADROWS / 16;               // 8192
    const int wBlocks = (NFILT * C_OUT + 15) / 16;     // 128
    pack_all_kernel<<<featBlocks + wBlocks, 512>>>(feat, weight, featBlocks);

    dim3 grid(XTILES, C_OUT / TILE_N);
    gemm_mma_kernel<<<grid, THREADS, SMEM_TOTAL>>>(bias, out);
}

// round 16
// speedup vs baseline: 1.4788x; 1.0027x over previous
#include <cuda_runtime.h>
#include <cuda_fp16.h>
#include <cstdint>

// ---------------------------------------------------------------------------
// SphericalLinear on GB300 (PTX target sm_103 plain: no tcgen05 available).
// R16: GEMM frozen at R15 (single-term fp16, KC=64, 3-stage cp.async ring,
//      one barrier/chunk, wait-group fix, 2 CTAs/SM, compact 516-tile grid).
//      Front-end FUSED: one kernel does classify + scatter + A-pack (a point's
//      packed row destination is final right after the block's atomicAdd), and
//      weight-pack rides along as extra blocks. 3 launches total.
// ---------------------------------------------------------------------------

#define NFILT   4
#define C_IN    256
#define C_OUT   512
#define TILE_M  128
#define TILE_N  128
#define KC      64
#define NCHUNKS (C_IN / KC)          // 4
#define NSTAGE  3
#define MAXP    65536
#define CAP     32768                 // fixed bucket capacity (rows)
#define PADROWS (NFILT * CAP)         // 131072
#define THREADS 256
#define XTILES  (MAXP / TILE_M + NFILT)   // 516: max total padded tiles
#define CB      256                   // classify/pack block size (points)

// SMEM: fp16 rows of 64 elems = 128B = 8 chunks of 16B, swizzle c^=(r&7)
#define MAT_SZ  (TILE_M * 128)        // 16384 B per matrix
#define OFF_AH  0
#define OFF_BH  (MAT_SZ)
#define STAGE_SZ (2 * MAT_SZ)         // 32768
#define SM_PERM  0
#define SM_TILE  1024
#define SMEM_TOTAL (SM_TILE + NSTAGE * STAGE_SZ)   // 99328 B (2/SM fits)

// ---- device scratch --------------------------------------------------------
__device__ int d_perm[PADROWS];
__device__ int d_fill[NFILT];
__device__ __half d_Ahi[(size_t)PADROWS * C_IN];
__device__ __half d_Whi[(size_t)NFILT * C_OUT * C_IN];

// ---- helpers ---------------------------------------------------------------
__device__ __forceinline__ uint32_t smem_u32(const void* p) {
    uint32_t a;
    asm("{ .reg .u64 t; cvta.to.shared.u64 t, %1; cvt.u32.u64 %0, t; }" : "=r"(a) : "l"(p));
    return a;
}
__device__ __forceinline__ void cp16(uint32_t dst, const void* src) {
    asm volatile("cp.async.cg.shared.global [%0], [%1], 16;" :: "r"(dst), "l"(src) : "memory");
}
#define CP_COMMIT() asm volatile("cp.async.commit_group;" ::: "memory")
#define CP_WAIT1()  asm volatile("cp.async.wait_group 1;" ::: "memory")
#define CP_WAIT0()  asm volatile("cp.async.wait_group 0;" ::: "memory")

__device__ __forceinline__ void ldsm4(uint32_t* r, uint32_t addr) {
    asm volatile("ldmatrix.sync.aligned.m8n8.x4.shared.b16 {%0,%1,%2,%3}, [%4];"
                 : "=r"(r[0]), "=r"(r[1]), "=r"(r[2]), "=r"(r[3]) : "r"(addr));
}
__device__ __forceinline__ void mma_f16(float* c, const uint32_t* a,
                                        uint32_t b0, uint32_t b1) {
    asm volatile("mma.sync.aligned.m16n8k16.row.col.f32.f16.f16.f32 "
                 "{%0,%1,%2,%3}, {%4,%5,%6,%7}, {%8,%9}, {%0,%1,%2,%3};"
                 : "+f"(c[0]), "+f"(c[1]), "+f"(c[2]), "+f"(c[3])
                 : "r"(a[0]), "r"(a[1]), "r"(a[2]), "r"(a[3]), "r"(b0), "r"(b1));
}

// fp32x8 -> fp16x8 packed
__device__ __forceinline__ uint4 cvt8_h(float4 v0, float4 v1) {
    uint4 hi;
    __half2 h0 = __floats2half2_rn(v0.x, v0.y);
    __half2 h1 = __floats2half2_rn(v0.z, v0.w);
    __half2 h2 = __floats2half2_rn(v1.x, v1.y);
    __half2 h3 = __floats2half2_rn(v1.z, v1.w);
    hi.x = *reinterpret_cast<uint32_t*>(&h0);
    hi.y = *reinterpret_cast<uint32_t*>(&h1);
    hi.z = *reinterpret_cast<uint32_t*>(&h2);
    hi.w = *reinterpret_cast<uint32_t*>(&h3);
    return hi;
}

// ---- front-end kernels -----------------------------------------------------
__global__ void reset_kernel() {
    int t = threadIdx.x;
    if (t < NFILT) d_fill[t] = 0;
}

// Fused classify + scatter + A-pack; weight-pack in trailing blocks.
// Classify blocks: CB points each. Phase 1 computes each point's packed row
// q (final right after this block's atomicAdd on d_fill) and writes d_perm.
// Phase 2: 8 warps x 32 rows gather-convert-pack feat rows to d_Ahi.
__global__ void classify_pack_kernel(const float* __restrict__ xyz,
                                     const float* __restrict__ feat,
                                     const float* __restrict__ weight,
                                     int P, int ncBlocks) {
    if ((int)blockIdx.x >= ncBlocks) {
        // ---- weight pack: 8 rows per block, one per warp ----
        int q = (blockIdx.x - ncBlocks) * 8 + (threadIdx.x >> 5);
        if (q >= NFILT * C_OUT) return;
        int col = (threadIdx.x & 31) * 8;
        const float4* src = (const float4*)(weight + (size_t)q * C_IN + col);
        *(uint4*)(d_Whi + (size_t)q * C_IN + col) = cvt8_h(src[0], src[1]);
        return;
    }

    __shared__ int sc[NFILT];
    __shared__ int sbase[NFILT];
    __shared__ int sQ[CB];
    int tid = threadIdx.x;
    if (tid < NFILT) sc[tid] = 0;
    __syncthreads();

    const int pbase = blockIdx.x * CB;
    int p = pbase + tid;
    int f = 0, rank = 0;
    if (p < P) {
        float x = xyz[3 * p + 0], y = xyz[3 * p + 1], z = xyz[3 * p + 2];
        float r = sqrtf(x * x + y * y + z * z);
        if      (r < 1.0f)   f = 0;
        else if (r < 1.5f)   f = 1;
        else if (r < 2.0f)   f = 2;
        else if (r < 100.0f) f = 3;
        else                 f = 0;   // argmax of all-False -> 0 (matches jnp)
        rank = atomicAdd(&sc[f], 1);
    }
    __syncthreads();
    if (tid < NFILT) sbase[tid] = (sc[tid] != 0) ? atomicAdd(&d_fill[tid], sc[tid]) : 0;
    __syncthreads();
    int q = -1;
    if (p < P) {
        q = f * CAP + sbase[f] + rank;
        d_perm[q] = p;
    }
    sQ[tid] = q;
    __syncthreads();

    // ---- phase 2: pack this block's points (8 warps x 32 rows) ----
    const int w = tid >> 5;
    const int col = (tid & 31) * 8;
    #pragma unroll 4
    for (int j = 0; j < CB / 8; j++) {
        int idx = w * (CB / 8) + j;
        int pp = pbase + idx;
        if (pp < P) {
            int qq = sQ[idx];
            const float4* src = (const float4*)(feat + (size_t)pp * C_IN + col);
            *(uint4*)(d_Ahi + (size_t)qq * C_IN + col) = cvt8_h(src[0], src[1]);
        }
    }
}

// ---- GEMM (identical to R15) -----------------------------------------------
__global__ void __launch_bounds__(THREADS, 2)
gemm_mma_kernel(const float* __restrict__ bias, float* __restrict__ out) {
    extern __shared__ char smem[];
    const int tid = threadIdx.x;
    const int lane = tid & 31;
    const int wid = tid >> 5;
    const int wm = wid >> 2;          // 0..1
    const int wn = wid & 3;           // 0..3
    const int by = blockIdx.y;

    // compact tile -> (filter, local tile) decode from bucket fills
    const int c0 = (d_fill[0] + TILE_M - 1) >> 7;
    const int c1 = (d_fill[1] + TILE_M - 1) >> 7;
    const int c2 = (d_fill[2] + TILE_M - 1) >> 7;
    const int c3 = (d_fill[3] + TILE_M - 1) >> 7;
    const int t = blockIdx.x;
    int f, lt;
    if      (t < c0)                { f = 0; lt = t; }
    else if (t < c0 + c1)           { f = 1; lt = t - c0; }
    else if (t < c0 + c1 + c2)      { f = 2; lt = t - c0 - c1; }
    else if (t < c0 + c1 + c2 + c3) { f = 3; lt = t - c0 - c1 - c2; }
    else return;

    const int rowbase = f * CAP + lt * TILE_M;     // padded global row base
    int nval = d_fill[f] - lt * TILE_M;
    if (nval > TILE_M) nval = TILE_M;

    int* sPerm = (int*)(smem + SM_PERM);
    if (tid < TILE_M) {
        sPerm[tid] = (tid < nval) ? d_perm[rowbase + tid] : d_perm[rowbase];
    }

    const uint32_t sb = smem_u32(smem) + SM_TILE;

    const char* srcA_h = (const char*)(d_Ahi + (size_t)rowbase * C_IN);
    const size_t wrow = ((size_t)f * C_OUT + (size_t)by * TILE_N) * C_IN;
    const char* srcB_h = (const char*)(d_Whi + wrow);

    // stage loader: 2 matrices x 128 rows x 8 swizzled 16B chunks
    auto load_stage = [&](int c, int s) {
        const int ktB = c * KC * 2;                 // byte offset into 512B rows
        const uint32_t base = sb + s * STAGE_SZ;
        #pragma unroll
        for (int it = 0; it < 4; it++) {
            int idx = it * THREADS + tid;           // 0..1023
            int r = idx >> 3;
            int cc = idx & 7;
            int sw = (cc ^ (r & 7)) * 16;
            uint32_t d0 = base + r * 128 + sw;
            size_t   so = (size_t)r * 512 + ktB + cc * 16;
            cp16(d0 + OFF_AH, srcA_h + so);
            cp16(d0 + OFF_BH, srcB_h + so);
        }
        CP_COMMIT();
    };

    load_stage(0, 0);
    load_stage(1, 1);

    // ldmatrix lane address components: swizzle selector (row&7) is per-lane
    // constant (16-row steps preserve it). Chunk index per k16 = k16*2 + kA.
    const int rA = ((lane >> 3) & 1) * 8 + (lane & 7);
    const int kA = (lane >> 4);
    const int rB = (lane >> 4) * 8 + (lane & 7);
    const int kB = ((lane >> 3) & 1);
    const int rowA0 = wm * 64 + rA;
    const int rowB0 = wn * 32 + rB;
    const int swzA = rowA0 & 7;
    const int swzB = rowB0 & 7;
    uint32_t adA[4], adB[4];
    #pragma unroll
    for (int k16 = 0; k16 < 4; k16++) {
        adA[k16] = (uint32_t)(rowA0 * 128 + (((k16 * 2 + kA) ^ swzA) * 16));
        adB[k16] = (uint32_t)(rowB0 * 128 + (((k16 * 2 + kB) ^ swzB) * 16));
    }

    float acc[4][4][4];
    #pragma unroll
    for (int i = 0; i < 4; i++)
        #pragma unroll
        for (int j = 0; j < 4; j++)
            #pragma unroll
            for (int e = 0; e < 4; e++) acc[i][j][e] = 0.0f;

    #pragma unroll
    for (int c = 0; c < NCHUNKS; c++) {
        const int s = c % NSTAGE;                  // static after full unroll
        const uint32_t base = sb + s * STAGE_SZ;
        // Wait accounting: group c must be complete; allowed pending = 1
        // except the LAST chunk, which must wait for everything.
        if (c == NCHUNKS - 1) { CP_WAIT0(); } else { CP_WAIT1(); }
        __syncthreads();                           // single barrier per chunk
        if (c + 2 < NCHUNKS) load_stage(c + 2, (c + 2) % NSTAGE);

        #pragma unroll
        for (int k16 = 0; k16 < 4; k16++) {
            const uint32_t aoff = base + adA[k16];
            const uint32_t boff = base + adB[k16];
            uint32_t ah[4][4];
            uint32_t bh[2][4];
            #pragma unroll
            for (int mi = 0; mi < 4; mi++) {
                ldsm4(ah[mi], aoff + mi * (16 * 128) + OFF_AH);
            }
            #pragma unroll
            for (int nj = 0; nj < 2; nj++) {
                ldsm4(bh[nj], boff + nj * (16 * 128) + OFF_BH);
            }
            #pragma unroll
            for (int mi = 0; mi < 4; mi++) {
                #pragma unroll
                for (int n8 = 0; n8 < 4; n8++) {
                    const int nj = n8 >> 1, h = (n8 & 1) * 2;
                    mma_f16(acc[mi][n8], ah[mi], bh[nj][h], bh[nj][h + 1]);
                }
            }
        }
    }

    // ---- epilogue: bias + scattered stores ----
    const int g = lane >> 2;
    const int a2 = (lane & 3) * 2;
    float2 bv[4];
    #pragma unroll
    for (int ni = 0; ni < 4; ni++)
        bv[ni] = *(const float2*)(bias + (size_t)f * C_OUT + by * TILE_N + wn * 32 + ni * 8 + a2);

    #pragma unroll
    for (int mi = 0; mi < 4; mi++) {
        #pragma unroll
        for (int half = 0; half < 2; half++) {
            int ml = wm * 64 + mi * 16 + g + half * 8;
            if (ml < nval) {
                float* orow = out + (size_t)sPerm[ml] * C_OUT + by * TILE_N + wn * 32;
                #pragma unroll
                for (int ni = 0; ni < 4; ni++) {
                    float2 v;
                    v.x = acc[mi][ni][half * 2 + 0] + bv[ni].x;
                    v.y = acc[mi][ni][half * 2 + 1] + bv[ni].y;
                    *(float2*)(orow + ni * 8 + a2) = v;
                }
            }
        }
    }
}

// ---------------------------------------------------------------------------
extern "C" void kernel_launch(void* const* d_in, const int* in_sizes, int n_in,
                              void* d_out, int out_size) {
    const float* feat   = (const float*)d_in[0];
    const float* xyz    = (const float*)d_in[1];
    const float* weight = (const float*)d_in[2];
    const float* bias   = (const float*)d_in[3];
    float* out = (float*)d_out;

    const int P = in_sizes[0] / C_IN;

    cudaFuncSetAttribute(gemm_mma_kernel,
                         cudaFuncAttributeMaxDynamicSharedMemorySize, SMEM_TOTAL);

    reset_kernel<<<1, 32>>>();

    const int ncBlocks = (P + CB - 1) / CB;            // 256
    const int wBlocks = (NFILT * C_OUT + 7) / 8;       // 256
    classify_pack_kernel<<<ncBlocks + wBlocks, CB>>>(xyz, feat, weight, P, ncBlocks);

    dim3 grid(XTILES, C_OUT / TILE_N);
    gemm_mma_kernel<<<grid, THREADS, SMEM_TOTAL>>>(bias, out);
}